// round 15
// baseline (speedup 1.0000x reference)
#include <cuda_runtime.h>
#include <cuda_bf16.h>

// Problem constants (fixed by the reference setup)
#define Bn 2
#define Pn 1024
#define Hn 128
#define Wn 128
#define NPIX (Hn * Wn)          // 16384
#define TILE_W 16
#define TILE_H 4
#define TSX (Wn / TILE_W)       // 8
#define TSY (Hn / TILE_H)       // 32
#define NT  (TSX * TSY)         // 256 tiles per camera
#define NBLK NT                 // 256 blocks; each renders its tile for BOTH cameras
#define TPB 512                 // 64 px * 8 depth segments in render phase
#define SEGPX 64
#define NSEG 8

// ---------------------------------------------------------------------------
// Scratch (device globals — no allocations allowed). Sorted-order attributes.
// ---------------------------------------------------------------------------
__device__ float4 g_s0[Bn * Pn];    // px, py, conA, conB   (depth-sorted)
__device__ float4 g_s1[Bn * Pn];    // conC, op, pthr(margin), 1/dep
__device__ float4 g_s2[Bn * Pn];    // rgb0, rgb1, rgb2, pad
__device__ float4 g_sbb[Bn * Pn];   // xmin, xmax, ymin, ymax (ellipse AABB)
__device__ unsigned g_bar;          // monotonic grid-barrier ticket counter

// SH constants
#define SH_C0 0.28209479177387814f
#define SH_C1 0.4886025119029199f
#define SH_C2_0 1.0925484305920792f
#define SH_C2_1 (-1.0925484305920792f)
#define SH_C2_2 0.31539156525252005f
#define SH_C2_3 (-1.0925484305920792f)
#define SH_C2_4 0.5462742152960396f
#define SH_C3_0 (-0.5900435899266435f)
#define SH_C3_1 2.890611442640554f
#define SH_C3_2 (-0.4570457994644658f)
#define SH_C3_3 0.3731763325901154f
#define SH_C3_4 (-0.4570457994644658f)
#define SH_C3_5 1.445305721320277f
#define SH_C3_6 (-0.5900435899266435f)

// Shared memory: phase 1 (depth table) and phase 2 (render) overlap via union.
struct PreS {
    float sd[Pn];            // per-camera depth table
    int   srank[8];          // ranks of this block's 8 gaussians
};
struct RndS {
    unsigned smw[32];        // ballot words
    int      sprefix[32];    // inclusive popc prefix
    short    slist[Pn];
    float4   s0[TPB], s1[TPB], s2[TPB];
    float4   pcol[TPB];
    float    pivd[TPB];
};

// ---------------------------------------------------------------------------
// Fused kernel: preprocess+sort (8 gaussians/block) -> grid barrier ->
// render (2 sequential tile passes, one per camera).
// grid = 256, block = 512. Co-residency needs only 2 blocks/SM (2x37KB smem,
// 32 regs) -- large slack vs 148 SMs * 4-block capacity.
// ---------------------------------------------------------------------------
__global__ __launch_bounds__(TPB, 4) void fused_kernel(
    const float* __restrict__ means,      // (P,3)
    const float* __restrict__ opac,       // (P,1)
    const float* __restrict__ scales,     // (P,3)
    const float* __restrict__ rots,       // (P,4)
    const float* __restrict__ sh,         // (P,16,3)
    const float* __restrict__ bg,         // (3)
    const float* __restrict__ viewm,      // (B,4,4) row-major
    const float* __restrict__ projm,      // (B,4,4)
    const float* __restrict__ campos,     // (B,3)
    const float* __restrict__ tanxs,      // (B)
    const float* __restrict__ tanys,      // (B)
    float* __restrict__ out)              // colors | invdepth | radii
{
    __shared__ union { PreS pre; RndS rnd; } sm;

    const int blk = blockIdx.x;
    const int tid = threadIdx.x;

    // =======================================================================
    // Phase 1: preprocess. Block handles 8 gaussians of camera pcam.
    // NO __syncthreads inside divergent branches.
    // =======================================================================
    {
        const int pcam  = blk >> 7;           // 128 blocks per camera
        const int chunk = blk & 127;          // 8 gaussians: chunk*8 ..
        const float* V  = viewm + pcam * 16;
        const float* PM = projm + pcam * 16;

        // depth table: thread t fills entries t and t+512 (uniform)
        const float v2 = V[2], v6 = V[6], v10 = V[10], v14 = V[14];
        #pragma unroll
        for (int k = 0; k < 2; k++) {
            const int g = tid + k * 512;
            sm.pre.sd[g] = means[g * 3 + 0] * v2 + means[g * 3 + 1] * v6
                         + means[g * 3 + 2] * v10 + v14;
        }
        __syncthreads();   // uniform

        // ---- rank warps: warps 0-7, one gaussian each (sync-free) ----
        if (tid < 256) {
            const int gl  = tid >> 5;          // 0..7
            const int sub = tid & 31;
            const int p   = chunk * 8 + gl;
            const float di = sm.pre.sd[p];
            int rank = 0;
            #pragma unroll 8
            for (int i = 0; i < 32; i++) {
                const int j = sub + 32 * i;    // conflict-free interleave
                const float dj = sm.pre.sd[j];
                rank += (dj < di) || (dj == di && j < p);
            }
            #pragma unroll
            for (int o = 1; o < 32; o <<= 1)
                rank += __shfl_xor_sync(0xffffffffu, rank, o);
            if (sub == 0) sm.pre.srank[gl] = rank;
        }

        // ---- math threads: tid 256..263 compute into registers (sync-free) --
        const bool is_math = (tid >= 256) && (tid < 264);
        float4 r_s0, r_s1, r_s2, r_bb;
        float  r_rad = 0.0f;
        int    r_p = 0;
        if (is_math) {
            const int local = tid - 256;
            const int p = chunk * 8 + local;
            r_p = p;
            const float tanx = tanxs[pcam], tany = tanys[pcam];
            const float mx = means[p * 3 + 0];
            const float my = means[p * 3 + 1];
            const float mz = means[p * 3 + 2];

            const float tx = mx * V[0] + my * V[4] + mz * V[8]  + V[12];
            const float ty = mx * V[1] + my * V[5] + mz * V[9]  + V[13];
            const float depth = sm.pre.sd[p];

            const float pp0 = mx * PM[0] + my * PM[4] + mz * PM[8]  + PM[12];
            const float pp1 = mx * PM[1] + my * PM[5] + mz * PM[9]  + PM[13];
            const float pp3 = mx * PM[3] + my * PM[7] + mz * PM[11] + PM[15];
            const float inw = 1.0f / (pp3 + 1e-7f);
            const float ndx = pp0 * inw, ndy = pp1 * inw;

            const float fx = (float)Wn / (2.0f * tanx);
            const float fy = (float)Hn / (2.0f * tany);
            const float tz = fmaxf(depth, 1e-6f);
            const float lx = 1.3f * tanx, ly = 1.3f * tany;
            const float txc = fminf(fmaxf(tx / tz, -lx), lx) * tz;
            const float tyc = fminf(fmaxf(ty / tz, -ly), ly) * tz;

            const float J00 = fx / tz, J02 = -fx * txc / (tz * tz);
            const float J11 = fy / tz, J12 = -fy * tyc / (tz * tz);

            float T2r0[3], T2r1[3];
            #pragma unroll
            for (int c = 0; c < 3; c++) {
                T2r0[c] = J00 * V[c * 4 + 0] + J02 * V[c * 4 + 2];
                T2r1[c] = J11 * V[c * 4 + 1] + J12 * V[c * 4 + 2];
            }

            const float4 q = ((const float4*)rots)[p];
            const float qn = rsqrtf(q.x * q.x + q.y * q.y + q.z * q.z + q.w * q.w);
            const float r = q.x * qn, qx = q.y * qn, qy = q.z * qn, qz = q.w * qn;
            float R[3][3];
            R[0][0] = 1.f - 2.f * (qy * qy + qz * qz);
            R[0][1] = 2.f * (qx * qy - r * qz);
            R[0][2] = 2.f * (qx * qz + r * qy);
            R[1][0] = 2.f * (qx * qy + r * qz);
            R[1][1] = 1.f - 2.f * (qx * qx + qz * qz);
            R[1][2] = 2.f * (qy * qz - r * qx);
            R[2][0] = 2.f * (qx * qz - r * qy);
            R[2][1] = 2.f * (qy * qz + r * qx);
            R[2][2] = 1.f - 2.f * (qx * qx + qy * qy);

            const float s0v = scales[p * 3 + 0];
            const float s1v = scales[p * 3 + 1];
            const float s2v = scales[p * 3 + 2];
            const float sq[3] = { s0v * s0v, s1v * s1v, s2v * s2v };

            float Sig[3][3];
            #pragma unroll
            for (int i = 0; i < 3; i++)
                #pragma unroll
                for (int k = 0; k < 3; k++)
                    Sig[i][k] = R[i][0] * sq[0] * R[k][0]
                              + R[i][1] * sq[1] * R[k][1]
                              + R[i][2] * sq[2] * R[k][2];

            float M0[3], M1[3];
            #pragma unroll
            for (int k = 0; k < 3; k++) {
                M0[k] = T2r0[0] * Sig[0][k] + T2r0[1] * Sig[1][k] + T2r0[2] * Sig[2][k];
                M1[k] = T2r1[0] * Sig[0][k] + T2r1[1] * Sig[1][k] + T2r1[2] * Sig[2][k];
            }
            const float cov00 = M0[0] * T2r0[0] + M0[1] * T2r0[1] + M0[2] * T2r0[2];
            const float cov01 = M0[0] * T2r1[0] + M0[1] * T2r1[1] + M0[2] * T2r1[2];
            const float cov11 = M1[0] * T2r1[0] + M1[1] * T2r1[1] + M1[2] * T2r1[2];

            const float a  = cov00 + 0.3f;
            const float cc = cov11 + 0.3f;
            const float bb = cov01;
            const float det = a * cc - bb * bb;
            const bool valid = (det > 0.0f) && (depth > 0.2f);
            const float dets = valid ? det : 1.0f;
            const float conA =  cc / dets;
            const float conB = -bb / dets;
            const float conC =  a  / dets;
            const float mid = 0.5f * (a + cc);
            const float lam = mid + sqrtf(fmaxf(0.1f, mid * mid - det));
            r_rad = valid ? ceilf(3.0f * sqrtf(lam)) : 0.0f;

            const float px = ((ndx + 1.0f) * (float)Wn - 1.0f) * 0.5f;
            const float py = ((ndy + 1.0f) * (float)Hn - 1.0f) * 0.5f;

            const float dx0 = mx - campos[pcam * 3 + 0];
            const float dy0 = my - campos[pcam * 3 + 1];
            const float dz0 = mz - campos[pcam * 3 + 2];
            const float dinv = rsqrtf(dx0 * dx0 + dy0 * dy0 + dz0 * dz0);
            const float x = dx0 * dinv, y = dy0 * dinv, z = dz0 * dinv;
            const float xx = x * x, yy = y * y, zz = z * z;
            const float xy = x * y, yz = y * z, xz = x * z;
            float basis[16];
            basis[0]  = SH_C0;
            basis[1]  = -SH_C1 * y;
            basis[2]  =  SH_C1 * z;
            basis[3]  = -SH_C1 * x;
            basis[4]  = SH_C2_0 * xy;
            basis[5]  = SH_C2_1 * yz;
            basis[6]  = SH_C2_2 * (2.0f * zz - xx - yy);
            basis[7]  = SH_C2_3 * xz;
            basis[8]  = SH_C2_4 * (xx - yy);
            basis[9]  = SH_C3_0 * y * (3.0f * xx - yy);
            basis[10] = SH_C3_1 * xy * z;
            basis[11] = SH_C3_2 * y * (4.0f * zz - xx - yy);
            basis[12] = SH_C3_3 * z * (2.0f * zz - 3.0f * xx - 3.0f * yy);
            basis[13] = SH_C3_4 * x * (4.0f * zz - xx - yy);
            basis[14] = SH_C3_5 * z * (xx - yy);
            basis[15] = SH_C3_6 * x * (xx - 3.0f * yy);

            float rgb[3];
            #pragma unroll
            for (int c = 0; c < 3; c++) {
                float res = 0.0f;
                #pragma unroll
                for (int k = 0; k < 16; k++)
                    res += basis[k] * sh[p * 48 + k * 3 + c];
                rgb[c] = fmaxf(res + 0.5f, 0.0f);
            }

            const float op = valid ? opac[p] : 0.0f;
            const float invdep = 1.0f / tz;
            const float p0 = -logf(255.0f * op);     // op=0 -> +inf
            const float pthr = p0 - 1e-3f;

            if (valid && op > 0.0f) {
                const float ex = sqrtf(fmaxf(0.0f, -2.0f * p0 * a)) + 0.02f;
                const float ey = sqrtf(fmaxf(0.0f, -2.0f * p0 * cc)) + 0.02f;
                r_bb = make_float4(px - ex, px + ex, py - ey, py + ey);
            } else {
                r_bb = make_float4(1e9f, -1e9f, 1e9f, -1e9f);
            }
            r_s0 = make_float4(px, py, conA, conB);
            r_s1 = make_float4(conC, op, pthr, invdep);
            r_s2 = make_float4(rgb[0], rgb[1], rgb[2], 0.0f);
        }

        __syncthreads();   // uniform: ranks ready, math results in registers

        if (is_math) {
            const int rank = sm.pre.srank[tid - 256];
            const int dst = pcam * Pn + rank;
            g_s0[dst]  = r_s0;
            g_s1[dst]  = r_s1;
            g_s2[dst]  = r_s2;
            g_sbb[dst] = r_bb;
            out[Bn * 4 * NPIX + pcam * Pn + r_p] = r_rad;   // radii tail
        }
    }

    // =======================================================================
    // Grid barrier: monotonic ticket (replay-safe; 256 blocks, 2/SM needed).
    // =======================================================================
    __threadfence();
    __syncthreads();
    if (tid == 0) {
        const unsigned t = atomicAdd(&g_bar, 1u);
        const unsigned target = (t / NBLK + 1u) * NBLK;
        while (atomicAdd(&g_bar, 0u) < target) __nanosleep(128);
        __threadfence();
    }
    __syncthreads();

    // =======================================================================
    // Phase 2: render tile = blk for camera 0, then camera 1 (R13 body).
    // =======================================================================
    const int tile = blk;
    const int tx0 = (tile & (TSX - 1)) * TILE_W;
    const int ty0 = (tile >> 3) * TILE_H;
    const int lane = tid & 31;
    const int wid  = tid >> 5;           // 0..15
    const int px = tid & (SEGPX - 1);
    const int seg = tid >> 6;            // 0..7
    const int x = tx0 + (px & (TILE_W - 1));
    const int y = ty0 + (px >> 4);
    const float xf = (float)x, yf = (float)y;

    const float ftx0 = (float)tx0, fty0 = (float)ty0;
    const float ftx1 = ftx0 + (float)(TILE_W - 1);
    const float fty1 = fty0 + (float)(TILE_H - 1);

    for (int b = 0; b < Bn; b++) {
        __syncthreads();   // smem reuse across passes

        const float4* bbp = g_sbb + b * Pn;
        const float4* s0p = g_s0 + b * Pn;
        const float4* s1p = g_s1 + b * Pn;
        const float4* s2p = g_s2 + b * Pn;

        // ---- Phase A: AABB tests, 2 rounds of 512, ballots into smem ----
        unsigned hitbits = 0;
        #pragma unroll
        for (int c = 0; c < 2; c++) {
            const float4 bbv = bbp[c * TPB + tid];
            const bool h = (bbv.x <= ftx1) && (bbv.y >= ftx0) &&
                           (bbv.z <= fty1) && (bbv.w >= fty0);
            const unsigned m = __ballot_sync(0xffffffffu, h);
            if (h) hitbits |= (1u << c);
            if (lane == 0) sm.rnd.smw[c * 16 + wid] = m;
        }
        __syncthreads();

        // ---- warp 0: inclusive popc prefix over the 32 ballot words ----
        if (tid < 32) {
            int pc = __popc(sm.rnd.smw[tid]);
            #pragma unroll
            for (int o = 1; o < 32; o <<= 1) {
                const int n = __shfl_up_sync(0xffffffffu, pc, o);
                if (tid >= o) pc += n;
            }
            sm.rnd.sprefix[tid] = pc;
        }
        __syncthreads();
        const int total = sm.rnd.sprefix[31];

        // ---- Phase B: order-preserving positions from prefix table ----
        {
            const unsigned ltmask = (1u << lane) - 1u;
            #pragma unroll
            for (int c = 0; c < 2; c++) {
                if (hitbits & (1u << c)) {
                    const int wi = c * 16 + wid;
                    const unsigned wm = sm.rnd.smw[wi];
                    const int pos = sm.rnd.sprefix[wi] - __popc(wm)
                                  + __popc(wm & ltmask);
                    sm.rnd.slist[pos] = (short)(c * TPB + tid);
                }
            }
        }
        __syncthreads();

        // ---- Phase C: segmented gather + composite ----
        float RT = 1.0f, RC0 = 0.0f, RC1 = 0.0f, RC2 = 0.0f, Rivd = 0.0f;

        for (int lb = 0; lb < total; lb += TPB) {
            const int m = min(TPB, total - lb);
            if (tid < m) {
                const int gi = (int)sm.rnd.slist[lb + tid];
                sm.rnd.s0[tid] = s0p[gi];
                sm.rnd.s1[tid] = s1p[gi];
                sm.rnd.s2[tid] = s2p[gi];
            }
            __syncthreads();

            const int qlen = (m + NSEG - 1) >> 3;
            const int j0 = seg * qlen;
            const int j1 = min(j0 + qlen, m);

            float T = 1.0f, c0 = 0.0f, c1 = 0.0f, c2 = 0.0f, ivd = 0.0f;
            #pragma unroll 2
            for (int j = j0; j < j1; j++) {
                const float4 a0 = sm.rnd.s0[j];
                const float4 a1 = sm.rnd.s1[j];
                const float dx = xf - a0.x;
                const float dy = yf - a0.y;
                const float power = -0.5f * (a0.z * dx * dx + a1.x * dy * dy)
                                    - a0.w * dx * dy;
                if (power >= a1.z && power <= 0.0f) {
                    const float alpha = fminf(0.99f, a1.y * __expf(power));
                    if (alpha >= (1.0f / 255.0f)) {   // exact reference test
                        const float4 a2 = sm.rnd.s2[j];
                        const float wgt = T * alpha;
                        c0  += wgt * a2.x;
                        c1  += wgt * a2.y;
                        c2  += wgt * a2.z;
                        ivd += wgt * a1.w;
                        T *= (1.0f - alpha);
                    }
                }
            }
            sm.rnd.pcol[tid] = make_float4(c0, c1, c2, T);
            sm.rnd.pivd[tid] = ivd;
            __syncthreads();

            // fold 8 segments in depth order (one thread per pixel)
            if (tid < SEGPX) {
                #pragma unroll
                for (int s = 0; s < NSEG; s++) {
                    const float4 pc = sm.rnd.pcol[s * SEGPX + tid];
                    const float  iv = sm.rnd.pivd[s * SEGPX + tid];
                    RC0  += RT * pc.x;
                    RC1  += RT * pc.y;
                    RC2  += RT * pc.z;
                    Rivd += RT * iv;
                    RT   *= pc.w;
                }
            }
            if (lb + TPB < total) {
                if (__syncthreads_and(tid < SEGPX ? (RT < 2e-5f) : true)) break;
            }
        }

        if (tid < SEGPX) {
            const float bg0 = bg[0], bg1 = bg[1], bg2 = bg[2];
            out[((b * 3 + 0) * Hn + y) * Wn + x] = RC0 + RT * bg0;
            out[((b * 3 + 1) * Hn + y) * Wn + x] = RC1 + RT * bg1;
            out[((b * 3 + 2) * Hn + y) * Wn + x] = RC2 + RT * bg2;
            out[Bn * 3 * NPIX + b * NPIX + y * Wn + x] = Rivd;
        }
    }
}

// ---------------------------------------------------------------------------
extern "C" void kernel_launch(void* const* d_in, const int* in_sizes, int n_in,
                              void* d_out, int out_size)
{
    const float* means  = (const float*)d_in[0];
    const float* opac   = (const float*)d_in[1];
    const float* scales = (const float*)d_in[2];
    const float* rots   = (const float*)d_in[3];
    const float* sh     = (const float*)d_in[4];
    const float* bg     = (const float*)d_in[5];
    const float* viewm  = (const float*)d_in[6];
    const float* projm  = (const float*)d_in[7];
    const float* campos = (const float*)d_in[8];
    const float* tanxs  = (const float*)d_in[9];
    const float* tanys  = (const float*)d_in[10];
    float* out = (float*)d_out;

    fused_kernel<<<NBLK, TPB>>>(means, opac, scales, rots, sh, bg,
                                viewm, projm, campos, tanxs, tanys, out);
}

// round 16
// speedup vs baseline: 1.0465x; 1.0465x over previous
#include <cuda_runtime.h>
#include <cuda_bf16.h>

// Problem constants (fixed by the reference setup)
#define Bn 2
#define Pn 1024
#define Hn 128
#define Wn 128
#define NPIX (Hn * Wn)          // 16384
#define TILE_W 16
#define TILE_H 4
#define TSX (Wn / TILE_W)       // 8
#define TSY (Hn / TILE_H)       // 32
#define NT  (TSX * TSY)         // 256 tiles per camera
#define NBLK (Bn * NT)          // 512 blocks, one tile+camera each
#define TPB 512                 // 64 px * 8 depth segments in render phase
#define SEGPX 64
#define NSEG 8

// ---------------------------------------------------------------------------
// Scratch (device globals — no allocations allowed). Sorted-order attributes.
// ---------------------------------------------------------------------------
__device__ float4 g_s0[Bn * Pn];    // px, py, conA, conB   (depth-sorted)
__device__ float4 g_s1[Bn * Pn];    // conC, op, pthr(margin), 1/dep
__device__ float4 g_s2[Bn * Pn];    // rgb0, rgb1, rgb2, pad
__device__ float4 g_sbb[Bn * Pn];   // xmin, xmax, ymin, ymax (ellipse AABB)
__device__ unsigned g_bar;          // monotonic grid-barrier ticket counter

// SH constants
#define SH_C0 0.28209479177387814f
#define SH_C1 0.4886025119029199f
#define SH_C2_0 1.0925484305920792f
#define SH_C2_1 (-1.0925484305920792f)
#define SH_C2_2 0.31539156525252005f
#define SH_C2_3 (-1.0925484305920792f)
#define SH_C2_4 0.5462742152960396f
#define SH_C3_0 (-0.5900435899266435f)
#define SH_C3_1 2.890611442640554f
#define SH_C3_2 (-0.4570457994644658f)
#define SH_C3_3 0.3731763325901154f
#define SH_C3_4 (-0.4570457994644658f)
#define SH_C3_5 1.445305721320277f
#define SH_C3_6 (-0.5900435899266435f)

// Shared memory: phase 1 (depth table) and phase 2 (render) overlap via union.
struct PreS {
    float sd[Pn];            // per-camera depth table
    int   srank[4];          // ranks of this block's 4 gaussians
};
struct RndS {
    unsigned smw[32];        // ballot words
    int      sprefix[32];    // inclusive popc prefix
    short    slist[Pn];
    float4   s0[TPB], s1[TPB], s2[TPB];
    float4   pcol[TPB];
    float    pivd[TPB];
};

// ---------------------------------------------------------------------------
// Fused kernel: preprocess+sort (4 gaussians/block) -> grid barrier ->
// render (ONE tile for ONE camera per block).
// grid = 512, block = 512, regs capped 32, smem ~38KB ->
// 4 blocks/SM co-residency: 592 slots >= 512 blocks (slack 80).
// All __syncthreads in uniform control flow (R15-proven phase-1 pattern).
// ---------------------------------------------------------------------------
__global__ __launch_bounds__(TPB, 4) void fused_kernel(
    const float* __restrict__ means,      // (P,3)
    const float* __restrict__ opac,       // (P,1)
    const float* __restrict__ scales,     // (P,3)
    const float* __restrict__ rots,       // (P,4)
    const float* __restrict__ sh,         // (P,16,3)
    const float* __restrict__ bg,         // (3)
    const float* __restrict__ viewm,      // (B,4,4) row-major
    const float* __restrict__ projm,      // (B,4,4)
    const float* __restrict__ campos,     // (B,3)
    const float* __restrict__ tanxs,      // (B)
    const float* __restrict__ tanys,      // (B)
    float* __restrict__ out)              // colors | invdepth | radii
{
    __shared__ union { PreS pre; RndS rnd; } sm;

    const int blk = blockIdx.x;
    const int tid = threadIdx.x;
    const int b   = blk >> 8;             // camera (256 blocks each)

    // =======================================================================
    // Phase 1: preprocess. Block handles 4 gaussians of camera b.
    // All __syncthreads uniform; math threads compute into registers.
    // =======================================================================
    {
        const int chunk = blk & 255;          // 4 gaussians: chunk*4 ..
        const float* V  = viewm + b * 16;
        const float* PM = projm + b * 16;

        // depth table: thread t fills entries t and t+512 (uniform)
        const float v2 = V[2], v6 = V[6], v10 = V[10], v14 = V[14];
        #pragma unroll
        for (int k = 0; k < 2; k++) {
            const int g = tid + k * 512;
            sm.pre.sd[g] = means[g * 3 + 0] * v2 + means[g * 3 + 1] * v6
                         + means[g * 3 + 2] * v10 + v14;
        }
        __syncthreads();   // uniform

        // ---- rank warps 0-3: one gaussian each (sync-free) ----
        if (tid < 128) {
            const int gl  = tid >> 5;          // 0..3
            const int sub = tid & 31;
            const int p   = chunk * 4 + gl;
            const float di = sm.pre.sd[p];
            int rank = 0;
            #pragma unroll 8
            for (int i = 0; i < 32; i++) {
                const int j = sub + 32 * i;    // conflict-free interleave
                const float dj = sm.pre.sd[j];
                rank += (dj < di) || (dj == di && j < p);
            }
            #pragma unroll
            for (int o = 1; o < 32; o <<= 1)
                rank += __shfl_xor_sync(0xffffffffu, rank, o);
            if (sub == 0) sm.pre.srank[gl] = rank;
        }

        // ---- math threads tid 128..131: compute into registers (sync-free) --
        const bool is_math = (tid >= 128) && (tid < 132);
        float4 r_s0, r_s1, r_s2, r_bb;
        float  r_rad = 0.0f;
        int    r_p = 0;
        if (is_math) {
            const int local = tid - 128;
            const int p = chunk * 4 + local;
            r_p = p;
            const float tanx = tanxs[b], tany = tanys[b];
            const float mx = means[p * 3 + 0];
            const float my = means[p * 3 + 1];
            const float mz = means[p * 3 + 2];

            const float tx = mx * V[0] + my * V[4] + mz * V[8]  + V[12];
            const float ty = mx * V[1] + my * V[5] + mz * V[9]  + V[13];
            const float depth = sm.pre.sd[p];

            const float pp0 = mx * PM[0] + my * PM[4] + mz * PM[8]  + PM[12];
            const float pp1 = mx * PM[1] + my * PM[5] + mz * PM[9]  + PM[13];
            const float pp3 = mx * PM[3] + my * PM[7] + mz * PM[11] + PM[15];
            const float inw = 1.0f / (pp3 + 1e-7f);
            const float ndx = pp0 * inw, ndy = pp1 * inw;

            const float fx = (float)Wn / (2.0f * tanx);
            const float fy = (float)Hn / (2.0f * tany);
            const float tz = fmaxf(depth, 1e-6f);
            const float lx = 1.3f * tanx, ly = 1.3f * tany;
            const float txc = fminf(fmaxf(tx / tz, -lx), lx) * tz;
            const float tyc = fminf(fmaxf(ty / tz, -ly), ly) * tz;

            const float J00 = fx / tz, J02 = -fx * txc / (tz * tz);
            const float J11 = fy / tz, J12 = -fy * tyc / (tz * tz);

            float T2r0[3], T2r1[3];
            #pragma unroll
            for (int c = 0; c < 3; c++) {
                T2r0[c] = J00 * V[c * 4 + 0] + J02 * V[c * 4 + 2];
                T2r1[c] = J11 * V[c * 4 + 1] + J12 * V[c * 4 + 2];
            }

            const float4 q = ((const float4*)rots)[p];
            const float qn = rsqrtf(q.x * q.x + q.y * q.y + q.z * q.z + q.w * q.w);
            const float r = q.x * qn, qx = q.y * qn, qy = q.z * qn, qz = q.w * qn;
            float R[3][3];
            R[0][0] = 1.f - 2.f * (qy * qy + qz * qz);
            R[0][1] = 2.f * (qx * qy - r * qz);
            R[0][2] = 2.f * (qx * qz + r * qy);
            R[1][0] = 2.f * (qx * qy + r * qz);
            R[1][1] = 1.f - 2.f * (qx * qx + qz * qz);
            R[1][2] = 2.f * (qy * qz - r * qx);
            R[2][0] = 2.f * (qx * qz - r * qy);
            R[2][1] = 2.f * (qy * qz + r * qx);
            R[2][2] = 1.f - 2.f * (qx * qx + qy * qy);

            const float s0v = scales[p * 3 + 0];
            const float s1v = scales[p * 3 + 1];
            const float s2v = scales[p * 3 + 2];
            const float sq[3] = { s0v * s0v, s1v * s1v, s2v * s2v };

            float Sig[3][3];
            #pragma unroll
            for (int i = 0; i < 3; i++)
                #pragma unroll
                for (int k = 0; k < 3; k++)
                    Sig[i][k] = R[i][0] * sq[0] * R[k][0]
                              + R[i][1] * sq[1] * R[k][1]
                              + R[i][2] * sq[2] * R[k][2];

            float M0[3], M1[3];
            #pragma unroll
            for (int k = 0; k < 3; k++) {
                M0[k] = T2r0[0] * Sig[0][k] + T2r0[1] * Sig[1][k] + T2r0[2] * Sig[2][k];
                M1[k] = T2r1[0] * Sig[0][k] + T2r1[1] * Sig[1][k] + T2r1[2] * Sig[2][k];
            }
            const float cov00 = M0[0] * T2r0[0] + M0[1] * T2r0[1] + M0[2] * T2r0[2];
            const float cov01 = M0[0] * T2r1[0] + M0[1] * T2r1[1] + M0[2] * T2r1[2];
            const float cov11 = M1[0] * T2r1[0] + M1[1] * T2r1[1] + M1[2] * T2r1[2];

            const float a  = cov00 + 0.3f;
            const float cc = cov11 + 0.3f;
            const float bb = cov01;
            const float det = a * cc - bb * bb;
            const bool valid = (det > 0.0f) && (depth > 0.2f);
            const float dets = valid ? det : 1.0f;
            const float conA =  cc / dets;
            const float conB = -bb / dets;
            const float conC =  a  / dets;
            const float mid = 0.5f * (a + cc);
            const float lam = mid + sqrtf(fmaxf(0.1f, mid * mid - det));
            r_rad = valid ? ceilf(3.0f * sqrtf(lam)) : 0.0f;

            const float px = ((ndx + 1.0f) * (float)Wn - 1.0f) * 0.5f;
            const float py = ((ndy + 1.0f) * (float)Hn - 1.0f) * 0.5f;

            const float dx0 = mx - campos[b * 3 + 0];
            const float dy0 = my - campos[b * 3 + 1];
            const float dz0 = mz - campos[b * 3 + 2];
            const float dinv = rsqrtf(dx0 * dx0 + dy0 * dy0 + dz0 * dz0);
            const float x = dx0 * dinv, y = dy0 * dinv, z = dz0 * dinv;
            const float xx = x * x, yy = y * y, zz = z * z;
            const float xy = x * y, yz = y * z, xz = x * z;
            float basis[16];
            basis[0]  = SH_C0;
            basis[1]  = -SH_C1 * y;
            basis[2]  =  SH_C1 * z;
            basis[3]  = -SH_C1 * x;
            basis[4]  = SH_C2_0 * xy;
            basis[5]  = SH_C2_1 * yz;
            basis[6]  = SH_C2_2 * (2.0f * zz - xx - yy);
            basis[7]  = SH_C2_3 * xz;
            basis[8]  = SH_C2_4 * (xx - yy);
            basis[9]  = SH_C3_0 * y * (3.0f * xx - yy);
            basis[10] = SH_C3_1 * xy * z;
            basis[11] = SH_C3_2 * y * (4.0f * zz - xx - yy);
            basis[12] = SH_C3_3 * z * (2.0f * zz - 3.0f * xx - 3.0f * yy);
            basis[13] = SH_C3_4 * x * (4.0f * zz - xx - yy);
            basis[14] = SH_C3_5 * z * (xx - yy);
            basis[15] = SH_C3_6 * x * (xx - 3.0f * yy);

            float rgb[3];
            #pragma unroll
            for (int c = 0; c < 3; c++) {
                float res = 0.0f;
                #pragma unroll
                for (int k = 0; k < 16; k++)
                    res += basis[k] * sh[p * 48 + k * 3 + c];
                rgb[c] = fmaxf(res + 0.5f, 0.0f);
            }

            const float op = valid ? opac[p] : 0.0f;
            const float invdep = 1.0f / tz;
            const float p0 = -logf(255.0f * op);     // op=0 -> +inf
            const float pthr = p0 - 1e-3f;

            if (valid && op > 0.0f) {
                const float ex = sqrtf(fmaxf(0.0f, -2.0f * p0 * a)) + 0.02f;
                const float ey = sqrtf(fmaxf(0.0f, -2.0f * p0 * cc)) + 0.02f;
                r_bb = make_float4(px - ex, px + ex, py - ey, py + ey);
            } else {
                r_bb = make_float4(1e9f, -1e9f, 1e9f, -1e9f);
            }
            r_s0 = make_float4(px, py, conA, conB);
            r_s1 = make_float4(conC, op, pthr, invdep);
            r_s2 = make_float4(rgb[0], rgb[1], rgb[2], 0.0f);
        }

        __syncthreads();   // uniform: ranks ready, math results in registers

        if (is_math) {
            const int rank = sm.pre.srank[tid - 128];
            const int dst = b * Pn + rank;
            g_s0[dst]  = r_s0;
            g_s1[dst]  = r_s1;
            g_s2[dst]  = r_s2;
            g_sbb[dst] = r_bb;
            out[Bn * 4 * NPIX + b * Pn + r_p] = r_rad;   // radii tail
        }
    }

    // =======================================================================
    // Grid barrier: monotonic ticket (replay-safe; all 512 blocks resident).
    // =======================================================================
    __threadfence();
    __syncthreads();
    if (tid == 0) {
        const unsigned t = atomicAdd(&g_bar, 1u);
        const unsigned target = (t / NBLK + 1u) * NBLK;
        while (atomicAdd(&g_bar, 0u) < target) __nanosleep(128);
        __threadfence();
    }
    __syncthreads();

    // =======================================================================
    // Phase 2: render one tile for camera b (R13 body verbatim).
    // =======================================================================
    {
        const int tile = blk & (NT - 1);
        const int tx0 = (tile & (TSX - 1)) * TILE_W;
        const int ty0 = (tile >> 3) * TILE_H;
        const int lane = tid & 31;
        const int wid  = tid >> 5;           // 0..15
        const int px = tid & (SEGPX - 1);
        const int seg = tid >> 6;            // 0..7
        const int x = tx0 + (px & (TILE_W - 1));
        const int y = ty0 + (px >> 4);
        const float xf = (float)x, yf = (float)y;

        const float ftx0 = (float)tx0, fty0 = (float)ty0;
        const float ftx1 = ftx0 + (float)(TILE_W - 1);
        const float fty1 = fty0 + (float)(TILE_H - 1);

        const float4* bbp = g_sbb + b * Pn;
        const float4* s0p = g_s0 + b * Pn;
        const float4* s1p = g_s1 + b * Pn;
        const float4* s2p = g_s2 + b * Pn;

        // ---- Phase A: AABB tests, 2 rounds of 512, ballots into smem ----
        unsigned hitbits = 0;
        #pragma unroll
        for (int c = 0; c < 2; c++) {
            const float4 bbv = bbp[c * TPB + tid];
            const bool h = (bbv.x <= ftx1) && (bbv.y >= ftx0) &&
                           (bbv.z <= fty1) && (bbv.w >= fty0);
            const unsigned m = __ballot_sync(0xffffffffu, h);
            if (h) hitbits |= (1u << c);
            if (lane == 0) sm.rnd.smw[c * 16 + wid] = m;
        }
        __syncthreads();

        // ---- warp 0: inclusive popc prefix over the 32 ballot words ----
        if (tid < 32) {
            int pc = __popc(sm.rnd.smw[tid]);
            #pragma unroll
            for (int o = 1; o < 32; o <<= 1) {
                const int n = __shfl_up_sync(0xffffffffu, pc, o);
                if (tid >= o) pc += n;
            }
            sm.rnd.sprefix[tid] = pc;
        }
        __syncthreads();
        const int total = sm.rnd.sprefix[31];

        // ---- Phase B: order-preserving positions from prefix table ----
        {
            const unsigned ltmask = (1u << lane) - 1u;
            #pragma unroll
            for (int c = 0; c < 2; c++) {
                if (hitbits & (1u << c)) {
                    const int wi = c * 16 + wid;
                    const unsigned wm = sm.rnd.smw[wi];
                    const int pos = sm.rnd.sprefix[wi] - __popc(wm)
                                  + __popc(wm & ltmask);
                    sm.rnd.slist[pos] = (short)(c * TPB + tid);
                }
            }
        }
        __syncthreads();

        // ---- Phase C: segmented gather + composite ----
        float RT = 1.0f, RC0 = 0.0f, RC1 = 0.0f, RC2 = 0.0f, Rivd = 0.0f;

        for (int lb = 0; lb < total; lb += TPB) {
            const int m = min(TPB, total - lb);
            if (tid < m) {
                const int gi = (int)sm.rnd.slist[lb + tid];
                sm.rnd.s0[tid] = s0p[gi];
                sm.rnd.s1[tid] = s1p[gi];
                sm.rnd.s2[tid] = s2p[gi];
            }
            __syncthreads();

            const int qlen = (m + NSEG - 1) >> 3;
            const int j0 = seg * qlen;
            const int j1 = min(j0 + qlen, m);

            float T = 1.0f, c0 = 0.0f, c1 = 0.0f, c2 = 0.0f, ivd = 0.0f;
            #pragma unroll 2
            for (int j = j0; j < j1; j++) {
                const float4 a0 = sm.rnd.s0[j];
                const float4 a1 = sm.rnd.s1[j];
                const float dx = xf - a0.x;
                const float dy = yf - a0.y;
                const float power = -0.5f * (a0.z * dx * dx + a1.x * dy * dy)
                                    - a0.w * dx * dy;
                if (power >= a1.z && power <= 0.0f) {
                    const float alpha = fminf(0.99f, a1.y * __expf(power));
                    if (alpha >= (1.0f / 255.0f)) {   // exact reference test
                        const float4 a2 = sm.rnd.s2[j];
                        const float wgt = T * alpha;
                        c0  += wgt * a2.x;
                        c1  += wgt * a2.y;
                        c2  += wgt * a2.z;
                        ivd += wgt * a1.w;
                        T *= (1.0f - alpha);
                    }
                }
            }
            sm.rnd.pcol[tid] = make_float4(c0, c1, c2, T);
            sm.rnd.pivd[tid] = ivd;
            __syncthreads();

            // fold 8 segments in depth order (one thread per pixel)
            if (tid < SEGPX) {
                #pragma unroll
                for (int s = 0; s < NSEG; s++) {
                    const float4 pc = sm.rnd.pcol[s * SEGPX + tid];
                    const float  iv = sm.rnd.pivd[s * SEGPX + tid];
                    RC0  += RT * pc.x;
                    RC1  += RT * pc.y;
                    RC2  += RT * pc.z;
                    Rivd += RT * iv;
                    RT   *= pc.w;
                }
            }
            if (lb + TPB < total) {
                if (__syncthreads_and(tid < SEGPX ? (RT < 2e-5f) : true)) break;
            }
        }

        if (tid < SEGPX) {
            const float bg0 = bg[0], bg1 = bg[1], bg2 = bg[2];
            out[((b * 3 + 0) * Hn + y) * Wn + x] = RC0 + RT * bg0;
            out[((b * 3 + 1) * Hn + y) * Wn + x] = RC1 + RT * bg1;
            out[((b * 3 + 2) * Hn + y) * Wn + x] = RC2 + RT * bg2;
            out[Bn * 3 * NPIX + b * NPIX + y * Wn + x] = Rivd;
        }
    }
}

// ---------------------------------------------------------------------------
extern "C" void kernel_launch(void* const* d_in, const int* in_sizes, int n_in,
                              void* d_out, int out_size)
{
    const float* means  = (const float*)d_in[0];
    const float* opac   = (const float*)d_in[1];
    const float* scales = (const float*)d_in[2];
    const float* rots   = (const float*)d_in[3];
    const float* sh     = (const float*)d_in[4];
    const float* bg     = (const float*)d_in[5];
    const float* viewm  = (const float*)d_in[6];
    const float* projm  = (const float*)d_in[7];
    const float* campos = (const float*)d_in[8];
    const float* tanxs  = (const float*)d_in[9];
    const float* tanys  = (const float*)d_in[10];
    float* out = (float*)d_out;

    fused_kernel<<<NBLK, TPB>>>(means, opac, scales, rots, sh, bg,
                                viewm, projm, campos, tanxs, tanys, out);
}

// round 17
// speedup vs baseline: 1.1975x; 1.1443x over previous
#include <cuda_runtime.h>
#include <cuda_bf16.h>

// Problem constants (fixed by the reference setup)
#define Bn 2
#define Pn 1024
#define Hn 128
#define Wn 128
#define NPIX (Hn * Wn)          // 16384
#define TILE_W 16
#define TILE_H 4
#define TSX (Wn / TILE_W)       // 8
#define TSY (Hn / TILE_H)       // 32
#define NT  (TSX * TSY)         // 256 tiles per camera
#define RTPB 512                // render threads: 64 px * 8 depth segments
#define SEGPX 64
#define NSEG 8
#define PRE_TPB 288             // 32 math + 256 rank threads

// ---------------------------------------------------------------------------
// Scratch (device globals — no allocations allowed). Sorted-order attributes.
// ---------------------------------------------------------------------------
__device__ float4 g_s0[Bn * Pn];    // px, py, conA, conB   (depth-sorted)
__device__ float4 g_s1[Bn * Pn];    // conC, op, pthr(margin), 1/dep
__device__ float4 g_s2[Bn * Pn];    // rgb0, rgb1, rgb2, pad
__device__ float4 g_sbb[Bn * Pn];   // xmin, xmax, ymin, ymax (ellipse AABB)

// SH constants
#define SH_C0 0.28209479177387814f
#define SH_C1 0.4886025119029199f
#define SH_C2_0 1.0925484305920792f
#define SH_C2_1 (-1.0925484305920792f)
#define SH_C2_2 0.31539156525252005f
#define SH_C2_3 (-1.0925484305920792f)
#define SH_C2_4 0.5462742152960396f
#define SH_C3_0 (-0.5900435899266435f)
#define SH_C3_1 2.890611442640554f
#define SH_C3_2 (-0.4570457994644658f)
#define SH_C3_3 0.3731763325901154f
#define SH_C3_4 (-0.4570457994644658f)
#define SH_C3_5 1.445305721320277f
#define SH_C3_6 (-0.5900435899266435f)

// ---------------------------------------------------------------------------
// Kernel 1: preprocess with role-split warps (R13 verbatim).
// grid = (Bn, 32), block = 288: 32 gaussians/block.
// ---------------------------------------------------------------------------
__global__ __launch_bounds__(PRE_TPB) void preprocess_kernel(
    const float* __restrict__ means,      // (P,3)
    const float* __restrict__ opac,       // (P,1)
    const float* __restrict__ scales,     // (P,3)
    const float* __restrict__ rots,       // (P,4)
    const float* __restrict__ sh,         // (P,16,3)
    const float* __restrict__ viewm,      // (B,4,4) row-major
    const float* __restrict__ projm,      // (B,4,4)
    const float* __restrict__ campos,     // (B,3)
    const float* __restrict__ tanxs,      // (B)
    const float* __restrict__ tanys,      // (B)
    float* __restrict__ out_radii)        // radii tail of output, (B,P)
{
    __shared__ float sd[Pn];              // full per-camera depth table
    __shared__ int   srank[8][32];

    const int b   = blockIdx.x;
    const int tid = threadIdx.x;
    const float* V  = viewm + b * 16;
    const float* PM = projm + b * 16;

    // Cooperative depth table: threads 0-127 build 8 entries each via float4.
    const float v2 = V[2], v6 = V[6], v10 = V[10], v14 = V[14];
    if (tid < 128) {
        const float4* m4 = (const float4*)means;
        float f[24];
        #pragma unroll
        for (int k = 0; k < 6; k++) {
            const float4 v = m4[tid * 6 + k];
            f[k * 4 + 0] = v.x; f[k * 4 + 1] = v.y;
            f[k * 4 + 2] = v.z; f[k * 4 + 3] = v.w;
        }
        #pragma unroll
        for (int i = 0; i < 8; i++)
            sd[tid * 8 + i] = f[3 * i] * v2 + f[3 * i + 1] * v6
                            + f[3 * i + 2] * v10 + v14;
    }
    __syncthreads();

    if (tid >= 32) {
        // ---- rank threads: stable 1/8-table scans (128 entries each) ----
        const int rt   = tid - 32;
        const int g32  = rt & 31;
        const int oct  = rt >> 5;              // 0..7
        const int p    = blockIdx.y * 32 + g32;
        const float di = sd[p];
        int rank = 0;
        const float4* sd4 = (const float4*)sd;
        const int j40 = oct * (Pn / 32);
        #pragma unroll 8
        for (int j4 = j40; j4 < j40 + Pn / 32; j4++) {
            const float4 v = sd4[j4];
            const int j = j4 * 4;
            rank += (v.x < di) || (v.x == di && (j + 0) < p);
            rank += (v.y < di) || (v.y == di && (j + 1) < p);
            rank += (v.z < di) || (v.z == di && (j + 2) < p);
            rank += (v.w < di) || (v.w == di && (j + 3) < p);
        }
        srank[oct][g32] = rank;
        __syncthreads();
        return;
    }

    // ---- math threads: full preprocess for one gaussian ----
    const int p = blockIdx.y * 32 + tid;
    const float tanx = tanxs[b], tany = tanys[b];
    const float mx = means[p * 3 + 0];
    const float my = means[p * 3 + 1];
    const float mz = means[p * 3 + 2];

    const float tx  = mx * V[0] + my * V[4] + mz * V[8]  + V[12];
    const float ty  = mx * V[1] + my * V[5] + mz * V[9]  + V[13];
    const float depth = sd[p];

    const float pp0 = mx * PM[0] + my * PM[4] + mz * PM[8]  + PM[12];
    const float pp1 = mx * PM[1] + my * PM[5] + mz * PM[9]  + PM[13];
    const float pp3 = mx * PM[3] + my * PM[7] + mz * PM[11] + PM[15];
    const float inw = 1.0f / (pp3 + 1e-7f);
    const float ndx = pp0 * inw, ndy = pp1 * inw;

    const float fx = (float)Wn / (2.0f * tanx);
    const float fy = (float)Hn / (2.0f * tany);
    const float tz = fmaxf(depth, 1e-6f);
    const float lx = 1.3f * tanx, ly = 1.3f * tany;
    const float txc = fminf(fmaxf(tx / tz, -lx), lx) * tz;
    const float tyc = fminf(fmaxf(ty / tz, -ly), ly) * tz;

    const float J00 = fx / tz, J02 = -fx * txc / (tz * tz);
    const float J11 = fy / tz, J12 = -fy * tyc / (tz * tz);

    float T2r0[3], T2r1[3];
    #pragma unroll
    for (int c = 0; c < 3; c++) {
        T2r0[c] = J00 * V[c * 4 + 0] + J02 * V[c * 4 + 2];
        T2r1[c] = J11 * V[c * 4 + 1] + J12 * V[c * 4 + 2];
    }

    const float4 q = ((const float4*)rots)[p];
    const float qn = rsqrtf(q.x * q.x + q.y * q.y + q.z * q.z + q.w * q.w);
    const float r = q.x * qn, qx = q.y * qn, qy = q.z * qn, qz = q.w * qn;
    float R[3][3];
    R[0][0] = 1.f - 2.f * (qy * qy + qz * qz);
    R[0][1] = 2.f * (qx * qy - r * qz);
    R[0][2] = 2.f * (qx * qz + r * qy);
    R[1][0] = 2.f * (qx * qy + r * qz);
    R[1][1] = 1.f - 2.f * (qx * qx + qz * qz);
    R[1][2] = 2.f * (qy * qz - r * qx);
    R[2][0] = 2.f * (qx * qz - r * qy);
    R[2][1] = 2.f * (qy * qz + r * qx);
    R[2][2] = 1.f - 2.f * (qx * qx + qy * qy);

    const float s0v = scales[p * 3 + 0];
    const float s1v = scales[p * 3 + 1];
    const float s2v = scales[p * 3 + 2];
    const float sq[3] = { s0v * s0v, s1v * s1v, s2v * s2v };

    float Sig[3][3];
    #pragma unroll
    for (int i = 0; i < 3; i++)
        #pragma unroll
        for (int k = 0; k < 3; k++)
            Sig[i][k] = R[i][0] * sq[0] * R[k][0]
                      + R[i][1] * sq[1] * R[k][1]
                      + R[i][2] * sq[2] * R[k][2];

    float M0[3], M1[3];
    #pragma unroll
    for (int k = 0; k < 3; k++) {
        M0[k] = T2r0[0] * Sig[0][k] + T2r0[1] * Sig[1][k] + T2r0[2] * Sig[2][k];
        M1[k] = T2r1[0] * Sig[0][k] + T2r1[1] * Sig[1][k] + T2r1[2] * Sig[2][k];
    }
    const float cov00 = M0[0] * T2r0[0] + M0[1] * T2r0[1] + M0[2] * T2r0[2];
    const float cov01 = M0[0] * T2r1[0] + M0[1] * T2r1[1] + M0[2] * T2r1[2];
    const float cov11 = M1[0] * T2r1[0] + M1[1] * T2r1[1] + M1[2] * T2r1[2];

    const float a  = cov00 + 0.3f;
    const float cc = cov11 + 0.3f;
    const float bb = cov01;
    const float det = a * cc - bb * bb;
    const bool valid = (det > 0.0f) && (depth > 0.2f);
    const float dets = valid ? det : 1.0f;
    const float conA =  cc / dets;
    const float conB = -bb / dets;
    const float conC =  a  / dets;
    const float mid = 0.5f * (a + cc);
    const float lam = mid + sqrtf(fmaxf(0.1f, mid * mid - det));
    const float radf = valid ? ceilf(3.0f * sqrtf(lam)) : 0.0f;

    const float px = ((ndx + 1.0f) * (float)Wn - 1.0f) * 0.5f;
    const float py = ((ndy + 1.0f) * (float)Hn - 1.0f) * 0.5f;

    const float dx0 = mx - campos[b * 3 + 0];
    const float dy0 = my - campos[b * 3 + 1];
    const float dz0 = mz - campos[b * 3 + 2];
    const float dinv = rsqrtf(dx0 * dx0 + dy0 * dy0 + dz0 * dz0);
    const float x = dx0 * dinv, y = dy0 * dinv, z = dz0 * dinv;
    const float xx = x * x, yy = y * y, zz = z * z;
    const float xy = x * y, yz = y * z, xz = x * z;
    float basis[16];
    basis[0]  = SH_C0;
    basis[1]  = -SH_C1 * y;
    basis[2]  =  SH_C1 * z;
    basis[3]  = -SH_C1 * x;
    basis[4]  = SH_C2_0 * xy;
    basis[5]  = SH_C2_1 * yz;
    basis[6]  = SH_C2_2 * (2.0f * zz - xx - yy);
    basis[7]  = SH_C2_3 * xz;
    basis[8]  = SH_C2_4 * (xx - yy);
    basis[9]  = SH_C3_0 * y * (3.0f * xx - yy);
    basis[10] = SH_C3_1 * xy * z;
    basis[11] = SH_C3_2 * y * (4.0f * zz - xx - yy);
    basis[12] = SH_C3_3 * z * (2.0f * zz - 3.0f * xx - 3.0f * yy);
    basis[13] = SH_C3_4 * x * (4.0f * zz - xx - yy);
    basis[14] = SH_C3_5 * z * (xx - yy);
    basis[15] = SH_C3_6 * x * (xx - 3.0f * yy);

    float shv[48];
    const float4* shp = (const float4*)(sh + p * 48);
    #pragma unroll
    for (int k = 0; k < 12; k++) {
        const float4 v = shp[k];
        shv[k * 4 + 0] = v.x; shv[k * 4 + 1] = v.y;
        shv[k * 4 + 2] = v.z; shv[k * 4 + 3] = v.w;
    }
    float rgb[3];
    #pragma unroll
    for (int c = 0; c < 3; c++) {
        float res = 0.0f;
        #pragma unroll
        for (int k = 0; k < 16; k++)
            res += basis[k] * shv[k * 3 + c];
        rgb[c] = fmaxf(res + 0.5f, 0.0f);
    }

    const float op = valid ? opac[p] : 0.0f;
    const float invdep = 1.0f / tz;
    const float p0   = -logf(255.0f * op);     // op=0 -> +inf
    const float pthr = p0 - 1e-3f;

    // Conservative AABB of {power >= p0}
    float4 aabb;
    if (valid && op > 0.0f) {
        const float ex = sqrtf(fmaxf(0.0f, -2.0f * p0 * a)) + 0.02f;
        const float ey = sqrtf(fmaxf(0.0f, -2.0f * p0 * cc)) + 0.02f;
        aabb = make_float4(px - ex, px + ex, py - ey, py + ey);
    } else {
        aabb = make_float4(1e9f, -1e9f, 1e9f, -1e9f);
    }

    __syncthreads();   // ranks ready

    const int rank = srank[0][tid] + srank[1][tid] + srank[2][tid] + srank[3][tid]
                   + srank[4][tid] + srank[5][tid] + srank[6][tid] + srank[7][tid];
    const int dst = b * Pn + rank;
    g_s0[dst]  = make_float4(px, py, conA, conB);
    g_s1[dst]  = make_float4(conC, op, pthr, invdep);
    g_s2[dst]  = make_float4(rgb[0], rgb[1], rgb[2], 0.0f);
    g_sbb[dst] = aabb;
    out_radii[b * Pn + p] = radf;    // radii stay in original order
}

// ---------------------------------------------------------------------------
// Kernel 2: render, 16x4 tile, 512 threads = 64 px * 8 depth segments.
// Direct compaction: hit threads write their own attributes straight to the
// compacted smem slot (pos < 512 always in practice); slist kept only for
// the defensive multi-chunk path. __launch_bounds__(512,4) -> single wave.
// PDL overlaps launch with preprocess. grid = Bn*NT = 512, block = 512.
// ---------------------------------------------------------------------------
__global__ __launch_bounds__(RTPB, 4) void render_kernel(
    const float* __restrict__ bg, float* __restrict__ out)
{
    __shared__ unsigned smw[32];         // ballot words, index = c*16+wid
    __shared__ int      sprefix[32];     // inclusive popc prefix
    __shared__ short    slist[Pn];
    __shared__ float4   s0[RTPB], s1[RTPB], s2[RTPB];
    __shared__ float4   pcol[RTPB];
    __shared__ float    pivd[RTPB];

    const int w = blockIdx.x;
    const int b    = w >> 8;                 // / NT
    const int tile = w & (NT - 1);
    const int tx0 = (tile & (TSX - 1)) * TILE_W;
    const int ty0 = (tile >> 3) * TILE_H;
    const int tid = threadIdx.x;
    const int lane = tid & 31;
    const int wid  = tid >> 5;               // 0..15
    const int px = tid & (SEGPX - 1);
    const int seg = tid >> 6;                // 0..7
    const int x = tx0 + (px & (TILE_W - 1));
    const int y = ty0 + (px >> 4);
    const float xf = (float)x, yf = (float)y;

    const float ftx0 = (float)tx0, fty0 = (float)ty0;
    const float ftx1 = ftx0 + (float)(TILE_W - 1);
    const float fty1 = fty0 + (float)(TILE_H - 1);

    const float4* bbp = g_sbb + b * Pn;
    const float4* s0p = g_s0 + b * Pn;
    const float4* s1p = g_s1 + b * Pn;
    const float4* s2p = g_s2 + b * Pn;

    // PDL: wait for preprocess results before first global read.
    cudaGridDependencySynchronize();

    // ---- Phase A: both AABB loads first (MLP=2), then ballots ----
    const float4 bb0 = bbp[tid];
    const float4 bb1 = bbp[RTPB + tid];
    const bool h0 = (bb0.x <= ftx1) && (bb0.y >= ftx0) &&
                    (bb0.z <= fty1) && (bb0.w >= fty0);
    const bool h1 = (bb1.x <= ftx1) && (bb1.y >= ftx0) &&
                    (bb1.z <= fty1) && (bb1.w >= fty0);
    const unsigned m0 = __ballot_sync(0xffffffffu, h0);
    const unsigned m1 = __ballot_sync(0xffffffffu, h1);
    if (lane == 0) { smw[wid] = m0; smw[16 + wid] = m1; }
    __syncthreads();

    // ---- warp 0: inclusive popc prefix over the 32 ballot words ----
    if (tid < 32) {
        int pc = __popc(smw[tid]);
        #pragma unroll
        for (int o = 1; o < 32; o <<= 1) {
            const int n = __shfl_up_sync(0xffffffffu, pc, o);
            if (tid >= o) pc += n;
        }
        sprefix[tid] = pc;
    }
    __syncthreads();
    const int total = sprefix[31];

    // ---- Phase B: direct compaction (and slist for the rare overflow path) --
    {
        const unsigned ltmask = (1u << lane) - 1u;
        if (h0) {
            const unsigned wm = smw[wid];
            const int pos = sprefix[wid] - __popc(wm) + __popc(wm & ltmask);
            slist[pos] = (short)tid;
            if (pos < RTPB) {
                s0[pos] = s0p[tid];
                s1[pos] = s1p[tid];
                s2[pos] = s2p[tid];
            }
        }
        if (h1) {
            const int wi = 16 + wid;
            const unsigned wm = smw[wi];
            const int pos = sprefix[wi] - __popc(wm) + __popc(wm & ltmask);
            slist[pos] = (short)(RTPB + tid);
            if (pos < RTPB) {
                s0[pos] = s0p[RTPB + tid];
                s1[pos] = s1p[RTPB + tid];
                s2[pos] = s2p[RTPB + tid];
            }
        }
    }
    __syncthreads();

    // ---- Phase C: segmented composite (chunk 0 pre-compacted) ----
    float RT = 1.0f, RC0 = 0.0f, RC1 = 0.0f, RC2 = 0.0f, Rivd = 0.0f;

    for (int lb = 0; lb < total; lb += RTPB) {
        const int m = min(RTPB, total - lb);
        if (lb > 0) {            // defensive overflow path (total > 512)
            __syncthreads();
            if (tid < m) {
                const int gi = (int)slist[lb + tid];
                s0[tid] = s0p[gi];
                s1[tid] = s1p[gi];
                s2[tid] = s2p[gi];
            }
            __syncthreads();
        }

        // this thread's contiguous eighth of [0, m)
        const int qlen = (m + NSEG - 1) >> 3;
        const int j0 = seg * qlen;
        const int j1 = min(j0 + qlen, m);

        float T = 1.0f, c0 = 0.0f, c1 = 0.0f, c2 = 0.0f, ivd = 0.0f;
        #pragma unroll 2
        for (int j = j0; j < j1; j++) {
            const float4 a0 = s0[j];
            const float4 a1 = s1[j];
            const float dx = xf - a0.x;
            const float dy = yf - a0.y;
            const float power = -0.5f * (a0.z * dx * dx + a1.x * dy * dy)
                                - a0.w * dx * dy;
            if (power >= a1.z && power <= 0.0f) {
                const float alpha = fminf(0.99f, a1.y * __expf(power));
                if (alpha >= (1.0f / 255.0f)) {   // exact reference test
                    const float4 a2 = s2[j];
                    const float wgt = T * alpha;
                    c0  += wgt * a2.x;
                    c1  += wgt * a2.y;
                    c2  += wgt * a2.z;
                    ivd += wgt * a1.w;
                    T *= (1.0f - alpha);
                }
            }
        }
        pcol[tid] = make_float4(c0, c1, c2, T);
        pivd[tid] = ivd;
        __syncthreads();

        // fold 8 segments in depth order into running state (one thread/px)
        if (tid < SEGPX) {
            #pragma unroll
            for (int s = 0; s < NSEG; s++) {
                const float4 pc = pcol[s * SEGPX + tid];
                const float  iv = pivd[s * SEGPX + tid];
                RC0  += RT * pc.x;
                RC1  += RT * pc.y;
                RC2  += RT * pc.z;
                Rivd += RT * iv;
                RT   *= pc.w;
            }
        }
    }

    if (tid < SEGPX) {
        const float bg0 = bg[0], bg1 = bg[1], bg2 = bg[2];
        out[((b * 3 + 0) * Hn + y) * Wn + x] = RC0 + RT * bg0;
        out[((b * 3 + 1) * Hn + y) * Wn + x] = RC1 + RT * bg1;
        out[((b * 3 + 2) * Hn + y) * Wn + x] = RC2 + RT * bg2;
        out[Bn * 3 * NPIX + b * NPIX + y * Wn + x] = Rivd;
    }
}

// ---------------------------------------------------------------------------
extern "C" void kernel_launch(void* const* d_in, const int* in_sizes, int n_in,
                              void* d_out, int out_size)
{
    const float* means  = (const float*)d_in[0];
    const float* opac   = (const float*)d_in[1];
    const float* scales = (const float*)d_in[2];
    const float* rots   = (const float*)d_in[3];
    const float* sh     = (const float*)d_in[4];
    const float* bg     = (const float*)d_in[5];
    const float* viewm  = (const float*)d_in[6];
    const float* projm  = (const float*)d_in[7];
    const float* campos = (const float*)d_in[8];
    const float* tanxs  = (const float*)d_in[9];
    const float* tanys  = (const float*)d_in[10];
    float* out = (float*)d_out;

    float* out_radii = out + Bn * 4 * NPIX;   // radii tail at 131072

    dim3 pre_grid(Bn, Pn / 32);
    preprocess_kernel<<<pre_grid, PRE_TPB>>>(means, opac, scales, rots, sh,
                                             viewm, projm, campos, tanxs, tanys,
                                             out_radii);

    // Render via PDL: its launch overlaps preprocess execution;
    // cudaGridDependencySynchronize() inside gates the data dependency.
    cudaLaunchConfig_t cfg = {};
    cfg.gridDim  = dim3(Bn * NT, 1, 1);
    cfg.blockDim = dim3(RTPB, 1, 1);
    cudaLaunchAttribute attrs[1];
    attrs[0].id = cudaLaunchAttributeProgrammaticStreamSerialization;
    attrs[0].val.programmaticStreamSerializationAllowed = 1;
    cfg.attrs = attrs;
    cfg.numAttrs = 1;
    cudaLaunchKernelEx(&cfg, render_kernel, (const float*)bg, (float*)out);
}